// round 6
// baseline (speedup 1.0000x reference)
#include <cuda_runtime.h>
#include <cuda_bf16.h>
#include <math.h>
#include <stdint.h>

#define BATCH 128
#define NPTS  1024
#define DIM   128
#define UMAX  0xFFFFFFFFu

// Scratch (device globals: allocation-free).
// g_D holds PACKED keys: high 22 bits = round-to-nearest of dist^2 float bits,
// low 10 bits = column index. Monotone in dist^2; ties break to lower index
// (matches jnp.argmin).
__device__ uint32_t       g_D[(size_t)BATCH * NPTS * NPTS];   // 512 MB
__device__ __nv_bfloat16  g_Xb[(size_t)BATCH * NPTS * DIM];   // 32 MB
__device__ float          g_norm[BATCH * NPTS];
__device__ float          g_partial[BATCH];

// ---------------------------------------------------------------------------
// Kernel 1: fused row norms (fp32 exact) + bf16 conversion. One warp per point.
// ---------------------------------------------------------------------------
__global__ void prep_kernel(const float* __restrict__ X) {
    int warp = (blockIdx.x * blockDim.x + threadIdx.x) >> 5;
    int lane = threadIdx.x & 31;
    if (warp >= BATCH * NPTS) return;
    const float4* row = (const float4*)(X + (size_t)warp * DIM);
    float4 v = row[lane];
    __nv_bfloat162* dst = (__nv_bfloat162*)(g_Xb + (size_t)warp * DIM) + lane * 2;
    dst[0] = __floats2bfloat162_rn(v.x, v.y);
    dst[1] = __floats2bfloat162_rn(v.z, v.w);
    float s = v.x * v.x + v.y * v.y + v.z * v.z + v.w * v.w;
    #pragma unroll
    for (int o = 16; o; o >>= 1) s += __shfl_down_sync(0xffffffffu, s, o);
    if (lane == 0) g_norm[warp] = s;
}

// ---------------------------------------------------------------------------
// Kernel 2: batched Gram via bf16 mma.sync; epilogue packs dist^2 keys.
// ---------------------------------------------------------------------------
#define KCH   64
#define LDR   72   // padded smem row length in bf16 (conflict-free)

__device__ __forceinline__ void mma16816(float* c, const uint32_t* a,
                                         uint32_t b0, uint32_t b1) {
    asm volatile(
        "mma.sync.aligned.m16n8k16.row.col.f32.bf16.bf16.f32 "
        "{%0,%1,%2,%3}, {%4,%5,%6,%7}, {%8,%9}, {%0,%1,%2,%3};\n"
        : "+f"(c[0]), "+f"(c[1]), "+f"(c[2]), "+f"(c[3])
        : "r"(a[0]), "r"(a[1]), "r"(a[2]), "r"(a[3]), "r"(b0), "r"(b1));
}

__device__ __forceinline__ uint32_t pack_key(float d2, int col) {
    return ((__float_as_uint(d2) + 0x200u) & 0xFFFFFC00u) | (uint32_t)col;
}

__global__ __launch_bounds__(256, 1)
void dist_kernel() {
    __shared__ __align__(16) __nv_bfloat16 As[128 * LDR];
    __shared__ __align__(16) __nv_bfloat16 Bs[128 * LDR];

    const int b  = blockIdx.z;
    const int I  = blockIdx.y * 128;
    const int J  = blockIdx.x * 128;
    const int tid  = threadIdx.x;
    const int lane = tid & 31;
    const int wid  = tid >> 5;
    const int wm   = wid & 3;
    const int wn   = wid >> 2;

    const __nv_bfloat16* Xb = g_Xb + (size_t)b * NPTS * DIM;

    float acc[2][8][4];
    #pragma unroll
    for (int m = 0; m < 2; ++m)
        #pragma unroll
        for (int n = 0; n < 8; ++n)
            #pragma unroll
            for (int q = 0; q < 4; ++q) acc[m][n][q] = 0.f;

    const uint32_t* As32 = (const uint32_t*)As;
    const uint32_t* Bs32 = (const uint32_t*)Bs;

    for (int k0 = 0; k0 < DIM; k0 += KCH) {
        __syncthreads();
        #pragma unroll
        for (int i = 0; i < 4; ++i) {
            int e  = tid + 256 * i;
            int r  = e >> 3;
            int c8 = e & 7;
            uint4 va = *(const uint4*)(Xb + (size_t)(I + r) * DIM + k0 + c8 * 8);
            uint4 vb = *(const uint4*)(Xb + (size_t)(J + r) * DIM + k0 + c8 * 8);
            *(uint4*)(As + r * LDR + c8 * 8) = va;
            *(uint4*)(Bs + r * LDR + c8 * 8) = vb;
        }
        __syncthreads();

        #pragma unroll
        for (int ks = 0; ks < KCH / 16; ++ks) {
            const int c = ks * 16 + (lane & 3) * 2;
            uint32_t a[2][4];
            #pragma unroll
            for (int mt = 0; mt < 2; ++mt) {
                int r0 = wm * 32 + mt * 16 + (lane >> 2);
                a[mt][0] = As32[(r0 * LDR + c) >> 1];
                a[mt][1] = As32[((r0 + 8) * LDR + c) >> 1];
                a[mt][2] = As32[(r0 * LDR + c + 8) >> 1];
                a[mt][3] = As32[((r0 + 8) * LDR + c + 8) >> 1];
            }
            #pragma unroll
            for (int nt = 0; nt < 8; ++nt) {
                int jr = wn * 64 + nt * 8 + (lane >> 2);
                uint32_t b0 = Bs32[(jr * LDR + c) >> 1];
                uint32_t b1 = Bs32[(jr * LDR + c + 8) >> 1];
                mma16816(acc[0][nt], a[0], b0, b1);
                mma16816(acc[1][nt], a[1], b0, b1);
            }
        }
    }

    uint32_t* Db = g_D + ((size_t)b << 20);
    const float* nb = g_norm + b * NPTS;
    #pragma unroll
    for (int mt = 0; mt < 2; ++mt) {
        int r0 = I + wm * 32 + mt * 16 + (lane >> 2);
        float ni0 = nb[r0], ni1 = nb[r0 + 8];
        #pragma unroll
        for (int nt = 0; nt < 8; ++nt) {
            int col = J + wn * 64 + nt * 8 + (lane & 3) * 2;
            float nj0 = nb[col], nj1 = nb[col + 1];
            uint2 v0, v1;
            v0.x = pack_key(fmaxf(ni0 + nj0 - 2.f * acc[mt][nt][0], 0.f), col);
            v0.y = pack_key(fmaxf(ni0 + nj1 - 2.f * acc[mt][nt][1], 0.f), col + 1);
            v1.x = pack_key(fmaxf(ni1 + nj0 - 2.f * acc[mt][nt][2], 0.f), col);
            v1.y = pack_key(fmaxf(ni1 + nj1 - 2.f * acc[mt][nt][3], 0.f), col + 1);
            *(uint2*)(Db + (size_t)r0 * NPTS + col)       = v0;
            *(uint2*)(Db + (size_t)(r0 + 8) * NPTS + col) = v1;
        }
    }
}

// ---------------------------------------------------------------------------
// Kernel 3: Prim's MST, one WARP per sample, fully register-resident mind.
// Lane owns 32 consecutive points (keys in 8 x uint4 registers).
//
// Visited sentinel = UMAX, and — the R3/R5 lesson — stickiness is EXPLICIT:
//   m_e = (m_e == UMAX || idx_e == j) ? UMAX : min(m_e, row_e)
// (for unsigned-min there is no value that both never wins and absorbs, so
// the absorb must be a select; real keys can't equal UMAX since d^2 is
// finite). idx_e is a per-element static offset, so no dynamic register
// indexing and no smem array at all.
// Top-2 speculation prefetches the runner-up's row to hide DRAM latency.
// ---------------------------------------------------------------------------
__device__ __forceinline__ uint32_t upd(uint32_t m, uint32_t r, int idx, int j) {
    uint32_t nx = min(m, r);
    return (m == UMAX || idx == j) ? UMAX : nx;
}

__global__ __launch_bounds__(32, 1)
void prim_kernel() {
    const int b    = blockIdx.x;
    const int lane = threadIdx.x;
    const uint32_t* Db = g_D + ((size_t)b << 20);
    const int base = lane * 32;

    // init: mind = row 0 (keys to start point); slot 0 marked visited
    uint4 m[8];
    #pragma unroll
    for (int k = 0; k < 8; ++k) m[k] = ((const uint4*)Db)[lane * 8 + k];
    if (lane == 0) m[0].x = UMAX;   // point 0

    float total = 0.f;
    int spec_idx = -1;
    uint4 SPEC[8];

    for (int it = 0; it < NPTS - 1; ++it) {
        // ---- per-lane min tree + warp REDUX (with runner-up) ----
        uint32_t t0[8];
        #pragma unroll
        for (int k = 0; k < 8; ++k)
            t0[k] = min(min(m[k].x, m[k].y), min(m[k].z, m[k].w));
        uint32_t km = min(min(min(t0[0], t0[1]), min(t0[2], t0[3])),
                          min(min(t0[4], t0[5]), min(t0[6], t0[7])));
        uint32_t best = __reduce_min_sync(0xffffffffu, km);
        uint32_t km2  = (km == best) ? UMAX : km;
        uint32_t second = __reduce_min_sync(0xffffffffu, km2);

        int j = (int)(best & 1023u);
        if (lane == 0) total += sqrtf(__uint_as_float(best & 0xFFFFFC00u));

        // ---- fetch row j (speculation hit: already in registers) ----
        uint4 R[8];
        if (j == spec_idx) {
            #pragma unroll
            for (int k = 0; k < 8; ++k) R[k] = SPEC[k];
        } else {
            const uint4* row = (const uint4*)(Db + ((size_t)j << 10));
            #pragma unroll
            for (int k = 0; k < 8; ++k) R[k] = row[lane * 8 + k];
        }
        // prefetch runner-up's row for next iteration
        int sj = (int)(second & 1023u);
        const uint4* srow = (const uint4*)(Db + ((size_t)sj << 10));
        #pragma unroll
        for (int k = 0; k < 8; ++k) SPEC[k] = srow[lane * 8 + k];
        spec_idx = (second == UMAX) ? -1 : sj;

        // ---- sticky min-update with fused visited-marking ----
        #pragma unroll
        for (int k = 0; k < 8; ++k) {
            m[k].x = upd(m[k].x, R[k].x, base + k * 4 + 0, j);
            m[k].y = upd(m[k].y, R[k].y, base + k * 4 + 1, j);
            m[k].z = upd(m[k].z, R[k].z, base + k * 4 + 2, j);
            m[k].w = upd(m[k].w, R[k].w, base + k * 4 + 3, j);
        }
    }
    if (lane == 0) g_partial[b] = total;
}

// ---------------------------------------------------------------------------
// Kernel 4: final scalar.
// ---------------------------------------------------------------------------
__global__ void final_kernel(float* __restrict__ out) {
    const int t = threadIdx.x;           // 128 threads
    const int lane = t & 31, wid = t >> 5;
    __shared__ float s[4];
    float v = g_partial[t];
    #pragma unroll
    for (int o = 16; o; o >>= 1) v += __shfl_down_sync(0xffffffffu, v, o);
    if (lane == 0) s[wid] = v;
    __syncthreads();
    if (t == 0) out[0] = (s[0] + s[1] + s[2] + s[3]) / (1023.f * (float)BATCH * 2.f);
}

// ---------------------------------------------------------------------------
extern "C" void kernel_launch(void* const* d_in, const int* in_sizes, int n_in,
                              void* d_out, int out_size) {
    (void)in_sizes; (void)n_in; (void)out_size;
    const float* X = (const float*)d_in[0];
    float* out = (float*)d_out;

    prep_kernel<<<16384, 256>>>(X);            // fused norms + bf16 convert
    dist_kernel<<<dim3(8, 8, BATCH), 256>>>();
    prim_kernel<<<BATCH, 32>>>();
    final_kernel<<<1, 128>>>(out);
}

// round 7
// speedup vs baseline: 1.3573x; 1.3573x over previous
#include <cuda_runtime.h>
#include <cuda_bf16.h>
#include <math.h>
#include <stdint.h>

#define BATCH 128
#define NPTS  1024
#define DIM   128
#define UMAX  0xFFFFFFFFu

// Scratch (device globals: allocation-free).
// g_D holds PACKED keys: high 22 bits = round-to-nearest of dist^2 float bits,
// low 10 bits = column index. Monotone in dist^2; ties -> lower index (matches
// jnp.argmin).
__device__ uint32_t       g_D[(size_t)BATCH * NPTS * NPTS];   // 512 MB
__device__ __nv_bfloat16  g_Xb[(size_t)BATCH * NPTS * DIM];   // 32 MB
__device__ float          g_norm[BATCH * NPTS];
__device__ float          g_partial[BATCH];

// ---------------------------------------------------------------------------
// Kernel 1: fused row norms (fp32 exact) + bf16 conversion. One warp per point.
// ---------------------------------------------------------------------------
__global__ void prep_kernel(const float* __restrict__ X) {
    int warp = (blockIdx.x * blockDim.x + threadIdx.x) >> 5;
    int lane = threadIdx.x & 31;
    if (warp >= BATCH * NPTS) return;
    const float4* row = (const float4*)(X + (size_t)warp * DIM);
    float4 v = row[lane];
    __nv_bfloat162* dst = (__nv_bfloat162*)(g_Xb + (size_t)warp * DIM) + lane * 2;
    dst[0] = __floats2bfloat162_rn(v.x, v.y);
    dst[1] = __floats2bfloat162_rn(v.z, v.w);
    float s = v.x * v.x + v.y * v.y + v.z * v.z + v.w * v.w;
    #pragma unroll
    for (int o = 16; o; o >>= 1) s += __shfl_down_sync(0xffffffffu, s, o);
    if (lane == 0) g_norm[warp] = s;
}

// ---------------------------------------------------------------------------
// Kernel 2: batched Gram via bf16 mma.sync; epilogue packs dist^2 keys.
// ---------------------------------------------------------------------------
#define KCH   64
#define LDR   72   // padded smem row length in bf16 (conflict-free)

__device__ __forceinline__ void mma16816(float* c, const uint32_t* a,
                                         uint32_t b0, uint32_t b1) {
    asm volatile(
        "mma.sync.aligned.m16n8k16.row.col.f32.bf16.bf16.f32 "
        "{%0,%1,%2,%3}, {%4,%5,%6,%7}, {%8,%9}, {%0,%1,%2,%3};\n"
        : "+f"(c[0]), "+f"(c[1]), "+f"(c[2]), "+f"(c[3])
        : "r"(a[0]), "r"(a[1]), "r"(a[2]), "r"(a[3]), "r"(b0), "r"(b1));
}

__device__ __forceinline__ uint32_t pack_key(float d2, int col) {
    return ((__float_as_uint(d2) + 0x200u) & 0xFFFFFC00u) | (uint32_t)col;
}

__global__ __launch_bounds__(256, 1)
void dist_kernel() {
    __shared__ __align__(16) __nv_bfloat16 As[128 * LDR];
    __shared__ __align__(16) __nv_bfloat16 Bs[128 * LDR];

    const int b  = blockIdx.z;
    const int I  = blockIdx.y * 128;
    const int J  = blockIdx.x * 128;
    const int tid  = threadIdx.x;
    const int lane = tid & 31;
    const int wid  = tid >> 5;
    const int wm   = wid & 3;
    const int wn   = wid >> 2;

    const __nv_bfloat16* Xb = g_Xb + (size_t)b * NPTS * DIM;

    float acc[2][8][4];
    #pragma unroll
    for (int m = 0; m < 2; ++m)
        #pragma unroll
        for (int n = 0; n < 8; ++n)
            #pragma unroll
            for (int q = 0; q < 4; ++q) acc[m][n][q] = 0.f;

    const uint32_t* As32 = (const uint32_t*)As;
    const uint32_t* Bs32 = (const uint32_t*)Bs;

    for (int k0 = 0; k0 < DIM; k0 += KCH) {
        __syncthreads();
        #pragma unroll
        for (int i = 0; i < 4; ++i) {
            int e  = tid + 256 * i;
            int r  = e >> 3;
            int c8 = e & 7;
            uint4 va = *(const uint4*)(Xb + (size_t)(I + r) * DIM + k0 + c8 * 8);
            uint4 vb = *(const uint4*)(Xb + (size_t)(J + r) * DIM + k0 + c8 * 8);
            *(uint4*)(As + r * LDR + c8 * 8) = va;
            *(uint4*)(Bs + r * LDR + c8 * 8) = vb;
        }
        __syncthreads();

        #pragma unroll
        for (int ks = 0; ks < KCH / 16; ++ks) {
            const int c = ks * 16 + (lane & 3) * 2;
            uint32_t a[2][4];
            #pragma unroll
            for (int mt = 0; mt < 2; ++mt) {
                int r0 = wm * 32 + mt * 16 + (lane >> 2);
                a[mt][0] = As32[(r0 * LDR + c) >> 1];
                a[mt][1] = As32[((r0 + 8) * LDR + c) >> 1];
                a[mt][2] = As32[(r0 * LDR + c + 8) >> 1];
                a[mt][3] = As32[((r0 + 8) * LDR + c + 8) >> 1];
            }
            #pragma unroll
            for (int nt = 0; nt < 8; ++nt) {
                int jr = wn * 64 + nt * 8 + (lane >> 2);
                uint32_t b0 = Bs32[(jr * LDR + c) >> 1];
                uint32_t b1 = Bs32[(jr * LDR + c + 8) >> 1];
                mma16816(acc[0][nt], a[0], b0, b1);
                mma16816(acc[1][nt], a[1], b0, b1);
            }
        }
    }

    uint32_t* Db = g_D + ((size_t)b << 20);
    const float* nb = g_norm + b * NPTS;
    #pragma unroll
    for (int mt = 0; mt < 2; ++mt) {
        int r0 = I + wm * 32 + mt * 16 + (lane >> 2);
        float ni0 = nb[r0], ni1 = nb[r0 + 8];
        #pragma unroll
        for (int nt = 0; nt < 8; ++nt) {
            int col = J + wn * 64 + nt * 8 + (lane & 3) * 2;
            float nj0 = nb[col], nj1 = nb[col + 1];
            uint2 v0, v1;
            v0.x = pack_key(fmaxf(ni0 + nj0 - 2.f * acc[mt][nt][0], 0.f), col);
            v0.y = pack_key(fmaxf(ni0 + nj1 - 2.f * acc[mt][nt][1], 0.f), col + 1);
            v1.x = pack_key(fmaxf(ni1 + nj0 - 2.f * acc[mt][nt][2], 0.f), col);
            v1.y = pack_key(fmaxf(ni1 + nj1 - 2.f * acc[mt][nt][3], 0.f), col + 1);
            *(uint2*)(Db + (size_t)r0 * NPTS + col)       = v0;
            *(uint2*)(Db + (size_t)(r0 + 8) * NPTS + col) = v1;
        }
    }
}

// ---------------------------------------------------------------------------
// Kernel 3: Prim's MST. 256 threads/CTA (8 warps for issue parallelism),
// each thread owns 4 CONSECUTIVE points, mind keys in one uint4 register.
// Sticky visited: m_e = (m_e==UMAX || idx_e==j) ? UMAX : min(m_e, row_e)
// (unsigned-min has no absorbing non-winning value -> explicit select;
// the R3/R5 lesson). Exact global (best, second) via per-warp REDUX pairs
// + 8-pair combine in warp 0; second's row is prefetched speculatively so a
// correct guess hides the ~577-cycle DRAM row fetch.
// ---------------------------------------------------------------------------
__device__ __forceinline__ uint32_t upd(uint32_t m, uint32_t r, int idx, int j) {
    uint32_t nx = min(m, r);
    return (m == UMAX || idx == j) ? UMAX : nx;
}

__global__ __launch_bounds__(256, 1)
void prim_kernel() {
    const int b    = blockIdx.x;
    const int tid  = threadIdx.x;
    const int lane = tid & 31;
    const int wid  = tid >> 5;
    const int p0   = tid * 4;          // first of this thread's 4 points

    const uint32_t* Db = g_D + ((size_t)b << 20);

    // init: mind = row 0 keys; point 0 marked visited
    uint4 m = ((const uint4*)Db)[tid];
    if (tid == 0) m.x = UMAX;

    __shared__ uint2    s_warp[8];     // per-warp (min, second)
    __shared__ uint2    s_bs;          // global (best, second)

    float total = 0.f;
    int spec_idx = -1;
    uint4 SPEC;

    for (int it = 0; it < NPTS - 1; ++it) {
        // ---- per-thread min of 4, then warp (min, second) via 2 REDUX ----
        uint32_t km = min(min(m.x, m.y), min(m.z, m.w));
        uint32_t wbest = __reduce_min_sync(0xffffffffu, km);
        uint32_t km2   = (km == wbest) ? UMAX : km;
        uint32_t wsec  = __reduce_min_sync(0xffffffffu, km2);
        if (lane == 0) s_warp[wid] = make_uint2(wbest, wsec);
        __syncthreads();

        // ---- warp 0 combines the 8 pairs (keys unique -> best is unique) ----
        if (wid == 0) {
            uint2 p = (lane < 8) ? s_warp[lane] : make_uint2(UMAX, UMAX);
            uint32_t gbest = __reduce_min_sync(0xffffffffu, p.x);
            // global second = min over: best-warp's second, other warps' mins
            uint32_t cand  = (p.x == gbest) ? p.y : min(p.x, p.y);
            uint32_t gsec  = __reduce_min_sync(0xffffffffu, cand);
            if (lane == 0) s_bs = make_uint2(gbest, gsec);
        }
        __syncthreads();

        uint2 bs = s_bs;
        int j = (int)(bs.x & 1023u);
        if (tid == 0) total += sqrtf(__uint_as_float(bs.x & 0xFFFFFC00u));

        // ---- row j: speculation hit -> already in registers ----
        uint4 R;
        if (j == spec_idx) {
            R = SPEC;
        } else {
            R = ((const uint4*)(Db + ((size_t)j << 10)))[tid];
        }
        // prefetch runner-up's row for next iteration
        int sj = (int)(bs.y & 1023u);
        SPEC = ((const uint4*)(Db + ((size_t)sj << 10)))[tid];
        spec_idx = (bs.y == UMAX) ? -1 : sj;

        // ---- sticky min-update with fused visited-marking ----
        m.x = upd(m.x, R.x, p0 + 0, j);
        m.y = upd(m.y, R.y, p0 + 1, j);
        m.z = upd(m.z, R.z, p0 + 2, j);
        m.w = upd(m.w, R.w, p0 + 3, j);
        // s_warp rewrite next iter is ordered by the two barriers above
    }
    if (tid == 0) g_partial[b] = total;
}

// ---------------------------------------------------------------------------
// Kernel 4: final scalar.
// ---------------------------------------------------------------------------
__global__ void final_kernel(float* __restrict__ out) {
    const int t = threadIdx.x;           // 128 threads
    const int lane = t & 31, wid = t >> 5;
    __shared__ float s[4];
    float v = g_partial[t];
    #pragma unroll
    for (int o = 16; o; o >>= 1) v += __shfl_down_sync(0xffffffffu, v, o);
    if (lane == 0) s[wid] = v;
    __syncthreads();
    if (t == 0) out[0] = (s[0] + s[1] + s[2] + s[3]) / (1023.f * (float)BATCH * 2.f);
}

// ---------------------------------------------------------------------------
extern "C" void kernel_launch(void* const* d_in, const int* in_sizes, int n_in,
                              void* d_out, int out_size) {
    (void)in_sizes; (void)n_in; (void)out_size;
    const float* X = (const float*)d_in[0];
    float* out = (float*)d_out;

    prep_kernel<<<16384, 256>>>(X);            // fused norms + bf16 convert
    dist_kernel<<<dim3(8, 8, BATCH), 256>>>();
    prim_kernel<<<BATCH, 256>>>();
    final_kernel<<<1, 128>>>(out);
}